// round 17
// baseline (speedup 1.0000x reference)
#include <cuda_runtime.h>
#include <cstdint>

// out[b,k,oc,x] = sum_ci W[k,oc,ci]*in[b,ci,k,x] + bias[k,oc]
// in: [4096,128,9,9]  w: [9,128,128]  bias: [9,128]  out: [4096,9,128,9] (f32)
//
// R17 = R16 with half-K stages: stage = 64ci x 72n (18KB), NBUF=3, wait_group 1.
// Syncs per CTA: 16 -> 8. All else identical (4Mx3N warps, 32x24 warp tile,
// packed-A g_W2, cp.async X, deferred sD epilogue).

#define KK     9
#define CIN    128
#define COUT   128
#define NB     8
#define TILES  4
#define NTHR   384
#define NBUF   3
#define NSTEP  (2 * TILES)      // 8 half-K steps per CTA

#define SXS 72                  // stage row stride (words): B-frag banks perfect
#define XH_WORDS (64 * SXS)     // 4608 words per half-stage (18432 B)
#define SDS 73                  // sD stride: copy-read banks distinct
#define SD_WORDS (128 * SDS)    // 9344 words (37376 B)
#define RING_WORDS (NBUF * XH_WORDS)       // 13824
#define SMEM_BYTES ((RING_WORDS + SD_WORDS) * 4)   // 92672 -> 2 CTAs/SM

// packed A-frags: [k][wm(4)][ks(16)][mf(2)][lane(32)][4] tf32 bits
#define W2_WORDS (KK * 4 * 16 * 2 * 32 * 4)   // 147456
__device__ uint32_t g_W2[W2_WORDS];

__device__ __forceinline__ uint32_t f2tf32(float f) {
    uint32_t u;
    asm("cvt.rna.tf32.f32 %0, %1;" : "=r"(u) : "f"(f));
    return u;
}
__device__ __forceinline__ uint32_t smem_u32(const void* p) {
    uint32_t a;
    asm("{ .reg .u64 t; cvta.to.shared.u64 t, %1; cvt.u32.u64 %0, t; }" : "=r"(a) : "l"(p));
    return a;
}
__device__ __forceinline__ void cp4(uint32_t dst, const float* src) {
    asm volatile("cp.async.ca.shared.global [%0], [%1], 4;" :: "r"(dst), "l"(src));
}
__device__ __forceinline__ void mma_tf32(float* d, const uint32_t* a, const uint32_t* b) {
    asm volatile(
        "mma.sync.aligned.m16n8k8.row.col.f32.tf32.tf32.f32 "
        "{%0,%1,%2,%3}, {%4,%5,%6,%7}, {%8,%9}, {%0,%1,%2,%3};"
        : "+f"(d[0]), "+f"(d[1]), "+f"(d[2]), "+f"(d[3])
        : "r"(a[0]), "r"(a[1]), "r"(a[2]), "r"(a[3]), "r"(b[0]), "r"(b[1]));
}

// ---- prep: w[9][128][128] f32 -> g_W2 packed tf32 A-frags ----
__global__ void prep_w_kernel(const float* __restrict__ w) {
    int idx = blockIdx.x * 256 + threadIdx.x;
    if (idx >= W2_WORDS) return;
    int j    = idx & 3;
    int lane = (idx >> 2) & 31;
    int mf   = (idx >> 7) & 1;
    int ks   = (idx >> 8) & 15;
    int wm   = (idx >> 12) & 3;
    int k    = idx >> 14;
    int g = lane >> 2, tl = lane & 3;
    int oc = wm * 32 + mf * 16 + g + (j & 1) * 8;
    int ci = ks * 8 + tl + ((j >> 1) & 1) * 4;
    g_W2[idx] = f2tf32(w[(k * COUT + oc) * CIN + ci]);
}

__global__ void __launch_bounds__(NTHR, 2)
gather_vertical_r17(const float* __restrict__ in,
                    const float* __restrict__ bias,
                    float* __restrict__ out)
{
    extern __shared__ uint32_t smem[];
    uint32_t* sX = smem;                        // 3 half-stages [64 ci][72 n]
    float*    sD = reinterpret_cast<float*>(smem + RING_WORDS);   // [128][73]

    const int tid = threadIdx.x;
    const int k   = blockIdx.x;
    const int yid = blockIdx.y;
    const int bbase = yid * TILES * NB;

    // ---- per-thread cp.async offsets (12 words per half-stage), loop-invariant ----
    const float* src = in + (size_t)bbase * (CIN * 81) + (size_t)k * 9;
    const uint32_t sx_base = smem_u32(sX);
    int goff[12], soff[12];
    #pragma unroll
    for (int j = 0; j < 12; j++) {
        int e  = tid + NTHR * j;      // 0..4607
        int q  = e / 9;               // bl*64 + ci_local
        int x  = e - 9 * q;
        int bl = q >> 6;
        int ci = q & 63;
        goff[j] = (bl * CIN + ci) * 81 + x;
        soff[j] = (ci * SXS + bl * 9 + x) * 4;
    }

    // ---- prologue: half-stages 0..1 ----
    #pragma unroll
    for (int s = 0; s < NBUF - 1; s++) {
        const int tn = s >> 1, hn = s & 1;
        const float* st = src + (size_t)(tn * NB) * (CIN * 81) + hn * 64 * 81;
        const uint32_t db = sx_base + s * (XH_WORDS * 4);
        #pragma unroll
        for (int j = 0; j < 12; j++) cp4(db + soff[j], st + goff[j]);
        asm volatile("cp.async.commit_group;" ::: "memory");
    }

    // ---- consumer identity: 12 warps = 4(M) x 3(N) ----
    const int wid  = tid >> 5, lane = tid & 31;
    const int g    = lane >> 2, tl = lane & 3;
    const int wm   = wid & 3;          // oc base wm*32
    const int wn   = wid >> 2;         // n  base wn*24
    const int n0   = wn * 24;
    const int rA   = wm * 32 + g;
    float bv[4];
    #pragma unroll
    for (int m = 0; m < 4; m++) bv[m] = bias[k * COUT + rA + m * 8];

    // packed A base: uint4 layout [k][wm][ks][mf][lane], 1024 uint4 per (k,wm)
    const uint4* wpbase = reinterpret_cast<const uint4*>(g_W2)
                          + (size_t)(k * 4 + wm) * 1024 + lane;

    const size_t out_tile_stride = (size_t)NB * 9 * 1152;
    float* obase = out + ((size_t)bbase * 9 + k) * 1152;

    float d[2][3][4];

    for (int s = 0; s < NSTEP; s++) {
        const int bi = s % NBUF;          // consuming buffer
        const int hi = s & 1;             // half within tile

        if (hi == 0) {
            #pragma unroll
            for (int mf = 0; mf < 2; mf++)
                #pragma unroll
                for (int nt = 0; nt < 3; nt++)
                    #pragma unroll
                    for (int j = 0; j < 4; j++) d[mf][nt][j] = 0.0f;
        }

        asm volatile("cp.async.wait_group 1;" ::: "memory");    // stage s arrived
        __syncthreads();                                         // also publishes sD writes

        // issue stage s+2 into buffer (s+2)%3 (freed by the sync above)
        if (s + 2 < NSTEP) {
            const int sn = s + 2, tn = sn >> 1, hn = sn & 1, bn = sn % NBUF;
            const float* st = src + (size_t)(tn * NB) * (CIN * 81) + hn * 64 * 81;
            const uint32_t db = sx_base + bn * (XH_WORDS * 4);
            #pragma unroll
            for (int j = 0; j < 12; j++) cp4(db + soff[j], st + goff[j]);
        }
        asm volatile("cp.async.commit_group;" ::: "memory");

        // ---- deferred epilogue copy for the PREVIOUS tile (overlaps this tile's MMA) ----
        if (hi == 0 && s >= 2) {
            const int tp = (s >> 1) - 1;
            float* ob = obase + (size_t)tp * out_tile_stride;
            #pragma unroll
            for (int i = tid, it = 0; it < 24; i += NTHR, it++) {
                int bl = i / 1152;
                int r  = i - bl * 1152;       // r = oc*9 + x
                int oc = r / 9;
                int x  = r - 9 * oc;
                ob[(size_t)bl * 10368 + r] = sD[oc * SDS + bl * 9 + x];
            }
        }

        // ---- MMA on buffer bi: 8 k-steps; per kstep: 2 LDG.128 A, 6 LDS B, 6 HMMA ----
        {
            const uint32_t* pb = sX + bi * XH_WORDS + tl * SXS + g + n0;
            #pragma unroll
            for (int kk2 = 0; kk2 < 8; kk2++) {
                const int ks = hi * 8 + kk2;
                uint4 av0 = wpbase[ks * 64];          // mf0
                uint4 av1 = wpbase[ks * 64 + 32];     // mf1
                uint32_t a0[4] = {av0.x, av0.y, av0.z, av0.w};
                uint32_t a1[4] = {av1.x, av1.y, av1.z, av1.w};

                uint32_t b[3][2];
                #pragma unroll
                for (int nt = 0; nt < 3; nt++) {
                    b[nt][0] = pb[nt * 8];
                    b[nt][1] = pb[4 * SXS + nt * 8];
                }
                #pragma unroll
                for (int nt = 0; nt < 3; nt++) {
                    mma_tf32(d[0][nt], a0, b[nt]);
                    mma_tf32(d[1][nt], a1, b[nt]);
                }
                pb += 8 * SXS;
            }
        }

        // ---- tile boundary: stage frags(+bias) into sD ----
        if (hi == 1) {
            #pragma unroll
            for (int mf = 0; mf < 2; mf++) {
                int ra = rA + mf * 16, rb = ra + 8;
                float bva = bv[mf * 2], bvb = bv[mf * 2 + 1];
                #pragma unroll
                for (int nt = 0; nt < 3; nt++) {
                    int n = n0 + nt * 8 + 2 * tl;
                    sD[ra * SDS + n]     = d[mf][nt][0] + bva;
                    sD[ra * SDS + n + 1] = d[mf][nt][1] + bva;
                    sD[rb * SDS + n]     = d[mf][nt][2] + bvb;
                    sD[rb * SDS + n + 1] = d[mf][nt][3] + bvb;
                }
            }
        }
    }

    // ---- flush last tile ----
    __syncthreads();
    {
        float* ob = obase + (size_t)(TILES - 1) * out_tile_stride;
        #pragma unroll
        for (int i = tid, it = 0; it < 24; i += NTHR, it++) {
            int bl = i / 1152;
            int r  = i - bl * 1152;
            int oc = r / 9;
            int x  = r - 9 * oc;
            ob[(size_t)bl * 10368 + r] = sD[oc * SDS + bl * 9 + x];
        }
    }
}

extern "C" void kernel_launch(void* const* d_in, const int* in_sizes, int n_in,
                              void* d_out, int out_size)
{
    const float* in   = (const float*)d_in[0];
    const float* w    = (const float*)d_in[1];
    const float* bias = (const float*)d_in[2];
    float* out        = (float*)d_out;

    int B = in_sizes[0] / (CIN * 81);        // 4096

    prep_w_kernel<<<(W2_WORDS + 255) / 256, 256>>>(w);

    cudaFuncSetAttribute(gather_vertical_r17,
                         cudaFuncAttributeMaxDynamicSharedMemorySize, SMEM_BYTES);

    dim3 grid(KK, B / (NB * TILES));         // (9, 128)
    gather_vertical_r17<<<grid, NTHR, SMEM_BYTES>>>(in, bias, out);
}